// round 12
// baseline (speedup 1.0000x reference)
#include <cuda_runtime.h>
#include <cuda_fp16.h>
#include <cstdint>
#include <cstddef>

// ---------------- problem dims ----------------
#define BB 8192
#define HH 1024
#define KTOT 2048            // concat K = I + H
#define NNI 4096             // interleaved gate dim n' = 4*h + g

// ---------------- GEMM tiling ----------------
#define BM 128
#define BN 128
#define THREADS 256                  // 8 warps: 2 (M) x 4 (N), warp tile 64x32
#define NSTAGES 3
#define KITERS2 32                   // mainloop iterations, 64 K each
#define SUB_A_U4 512                 // one 32-K subtile (128 rows) in uint4
#define SUB_B_U4 512
#define A_TILE_U4 (2 * SUB_A_U4)     // 64-K stage A = 1024 uint4 = 16KB
#define B_TILE_U4 (2 * SUB_B_U4)
#define A_BYTES (A_TILE_U4 * 16)     // 16384
#define B_BYTES (B_TILE_U4 * 16)     // 16384
#define STAGE_BYTES (A_BYTES + B_BYTES)        // 32768
#define STAGE_REGION (NSTAGES * STAGE_BYTES)   // 98304
#define EPI_STRIDE 132
#define EPI_BYTES (BM * EPI_STRIDE * 4)        // 67584 (overlays stage region)
#define OFF_BIAS STAGE_REGION
#define SMEM_TOTAL (STAGE_REGION + 512)        // 98816 -> 2 CTAs/SM

// ---------------- scratch: fragment-ordered fp16 operands ----------------
// g_A: [mb(64)][kt32(64)][m16(8)][ks(2)][lane(32)] x uint4
__device__ uint4 g_A[(size_t)BB * KTOT / 8];
// g_B: [nb(32)][kt32(64)][wn(4)][p(2)][ks(2)][lane(32)] x uint4
__device__ uint4 g_B[(size_t)NNI * KTOT / 8];
__device__ float g_bias[NNI];   // interleaved 4h+g

// ---------------- helpers ----------------
__device__ __forceinline__ void cpa16(uint32_t s, const void* g) {
    asm volatile("cp.async.cg.shared.global [%0], [%1], 16;" :: "r"(s), "l"(g));
}

__device__ __forceinline__ uint32_t h2pack(float lo, float hi) {
    __half2 h = __floats2half2_rn(lo, hi);
    return *reinterpret_cast<uint32_t*>(&h);
}

__device__ __forceinline__ void mma_f16(float* d, const uint4& a, uint32_t b0, uint32_t b1) {
    asm volatile(
        "mma.sync.aligned.m16n8k16.row.col.f32.f16.f16.f32 "
        "{%0,%1,%2,%3}, {%4,%5,%6,%7}, {%8,%9}, {%0,%1,%2,%3};"
        : "+f"(d[0]), "+f"(d[1]), "+f"(d[2]), "+f"(d[3])
        : "r"(a.x), "r"(a.y), "r"(a.z), "r"(a.w), "r"(b0), "r"(b1));
}

__device__ __forceinline__ float fast_sigmoid(float x) {
    return __fdividef(1.0f, 1.0f + __expf(-x));
}
__device__ __forceinline__ float fast_tanh(float x) {
    return __fmaf_rn(2.0f, __fdividef(1.0f, 1.0f + __expf(-2.0f * x)), -1.0f);
}

// ================= pre-pass (merged): fp16-round + concat + fragment-order =================
#define A_BLOCKS 8192   // 2^21 uint4 / 256
#define B_BLOCKS 4096   // 2^20 uint4 / 256

__global__ __launch_bounds__(256) void convert_AB(const float* __restrict__ X,
                                                  const float* __restrict__ Hs,
                                                  const float* __restrict__ Wx,
                                                  const float* __restrict__ Wh,
                                                  const float* __restrict__ bx,
                                                  const float* __restrict__ bh) {
    if (blockIdx.x < A_BLOCKS) {
        size_t idx = (size_t)blockIdx.x * 256 + threadIdx.x;
        int lane = (int)(idx & 31);
        int ks   = (int)((idx >> 5) & 1);
        int m16  = (int)((idx >> 6) & 7);
        int kt   = (int)((idx >> 9) & 63);
        int mb   = (int)(idx >> 15);
        int qr = lane >> 2, qc = lane & 3;
        int R = mb * 128 + m16 * 16 + qr;
        int C = kt * 32 + ks * 16 + 2 * qc;

        const float* src = (C < 1024) ? X : Hs;
        int c0 = C & 1023;
        float2 r0a = *(const float2*)&src[(size_t)R * 1024 + c0];
        float2 r0b = *(const float2*)&src[(size_t)R * 1024 + c0 + 8];
        float2 r1a = *(const float2*)&src[(size_t)(R + 8) * 1024 + c0];
        float2 r1b = *(const float2*)&src[(size_t)(R + 8) * 1024 + c0 + 8];

        uint4 o;
        o.x = h2pack(r0a.x, r0a.y);
        o.y = h2pack(r1a.x, r1a.y);
        o.z = h2pack(r0b.x, r0b.y);
        o.w = h2pack(r1b.x, r1b.y);
        g_A[idx] = o;
    } else {
        size_t idx = (size_t)(blockIdx.x - A_BLOCKS) * 256 + threadIdx.x;
        int lane = (int)(idx & 31);
        int ks   = (int)((idx >> 5) & 1);
        int p    = (int)((idx >> 6) & 1);
        int wn   = (int)((idx >> 7) & 3);
        int kt   = (int)((idx >> 9) & 63);
        int nb   = (int)(idx >> 15);
        int qr = lane >> 2, qc = lane & 3;
        int C = kt * 32 + ks * 16 + 2 * qc;
        int N0 = nb * 128 + wn * 32 + p * 16 + qr;
        int N1 = N0 + 8;
        int sr0 = (N0 & 3) * 1024 + (N0 >> 2);    // n' = 4h+g -> row g*1024+h
        int sr1 = (N1 & 3) * 1024 + (N1 >> 2);

        const float* src = (C < 1024) ? Wx : Wh;
        int c0 = C & 1023;
        float2 w0a = *(const float2*)&src[(size_t)sr0 * 1024 + c0];
        float2 w0b = *(const float2*)&src[(size_t)sr0 * 1024 + c0 + 8];
        float2 w1a = *(const float2*)&src[(size_t)sr1 * 1024 + c0];
        float2 w1b = *(const float2*)&src[(size_t)sr1 * 1024 + c0 + 8];

        uint4 o;
        o.x = h2pack(w0a.x, w0a.y);
        o.y = h2pack(w0b.x, w0b.y);
        o.z = h2pack(w1a.x, w1a.y);
        o.w = h2pack(w1b.x, w1b.y);
        g_B[idx] = o;

        if (kt == 0 && ks == 0 && qc == 0) {
            g_bias[N0] = bx[sr0] + bh[sr0];
            g_bias[N1] = bx[sr1] + bh[sr1];
        }
    }
}

// ================= fused GEMM + LSTM epilogue (2 CTAs/SM, 8 warps) =================
__global__ __launch_bounds__(THREADS, 2) void lstm_gemm(const float* __restrict__ cin,
                                                        float* __restrict__ out) {
    extern __shared__ char smem[];
    float* smf = (float*)smem;
    const int tid  = threadIdx.x;
    const int lane = tid & 31;
    const int wid  = tid >> 5;
    const int wm   = wid >> 2;      // 2 warps over M (64 rows each)
    const int wn   = wid & 3;       // 4 warps over N (32 cols each)
    const int qr   = lane >> 2;
    const int qc   = lane & 3;

    const int mb = blockIdx.y;      // 0..63
    const int nb = blockIdx.x;      // 0..31
    const int m_base = mb * BM;
    const int hb = nb * 32;

    uint32_t sb;
    asm("{ .reg .u64 t; cvta.to.shared.u64 t, %1; cvt.u32.u64 %0, t; }" : "=r"(sb) : "l"(smem));

    if (tid < 128) smf[OFF_BIAS / 4 + tid] = g_bias[nb * 128 + tid];

    float acc[4][4][4] = {};   // 4 m16-frags x 4 n8-frags

    const uint4* gA4 = g_A + ((size_t)mb * 64) * SUB_A_U4;
    const uint4* gB4 = g_B + ((size_t)nb * 64) * SUB_B_U4;

    // ---- prologue: fill stages 0..1 (2048 chunks / 256 threads = 8 each) ----
#pragma unroll
    for (int s = 0; s < NSTAGES - 1; s++) {
        uint32_t base = sb + (uint32_t)s * STAGE_BYTES;
        const uint4* a_src = gA4 + (size_t)s * A_TILE_U4;
        const uint4* b_src = gB4 + (size_t)s * B_TILE_U4;
#pragma unroll
        for (int j = 0; j < 4; j++) {
            int ch = j * THREADS + tid;
            cpa16(base + (uint32_t)ch * 16u, a_src + ch);
            cpa16(base + (uint32_t)(A_BYTES + ch * 16), b_src + ch);
        }
        asm volatile("cp.async.commit_group;");
    }

#pragma unroll 1
    for (int it = 0; it < KITERS2; ++it) {
        asm volatile("cp.async.wait_group %0;" :: "n"(NSTAGES - 2));
        __syncthreads();

        if (it + NSTAGES - 1 < KITERS2) {
            const int ns = (it + NSTAGES - 1) % NSTAGES;
            uint32_t base = sb + (uint32_t)ns * STAGE_BYTES;
            const uint4* a_src = gA4 + (size_t)(it + NSTAGES - 1) * A_TILE_U4;
            const uint4* b_src = gB4 + (size_t)(it + NSTAGES - 1) * B_TILE_U4;
#pragma unroll
            for (int j = 0; j < 4; j++) {
                int ch = j * THREADS + tid;
                cpa16(base + (uint32_t)ch * 16u, a_src + ch);
                cpa16(base + (uint32_t)(A_BYTES + ch * 16), b_src + ch);
            }
        }
        asm volatile("cp.async.commit_group;");   // empty commit in tail keeps count

        const int cur = it % NSTAGES;
        const uint4* sA = (const uint4*)(smem + cur * STAGE_BYTES) + lane;
        const uint4* sB = (const uint4*)(smem + cur * STAGE_BYTES + A_BYTES) + lane;

#pragma unroll
        for (int ks2 = 0; ks2 < 4; ks2++) {       // 4 x 16-K steps per iteration
            const int aoff = (ks2 >> 1) * SUB_A_U4 + (ks2 & 1) * 32;
            const int boff = (ks2 >> 1) * SUB_B_U4 + (ks2 & 1) * 32;
            uint4 a0 = sA[aoff + ((wm * 4 + 0) * 2) * 32];
            uint4 a1 = sA[aoff + ((wm * 4 + 1) * 2) * 32];
            uint4 a2 = sA[aoff + ((wm * 4 + 2) * 2) * 32];
            uint4 a3 = sA[aoff + ((wm * 4 + 3) * 2) * 32];
            uint4 b0 = sB[boff + ((wn * 2 + 0) * 2) * 32];
            uint4 b1 = sB[boff + ((wn * 2 + 1) * 2) * 32];
#pragma unroll
            for (int mf = 0; mf < 4; mf++) {
                const uint4& a = (mf == 0) ? a0 : (mf == 1) ? a1 : (mf == 2) ? a2 : a3;
                mma_f16(acc[mf][0], a, b0.x, b0.y);
                mma_f16(acc[mf][1], a, b0.z, b0.w);
                mma_f16(acc[mf][2], a, b1.x, b1.y);
                mma_f16(acc[mf][3], a, b1.z, b1.w);
            }
        }
    }

    // ---------------- fused epilogue ----------------
    asm volatile("cp.async.wait_group 0;");
    __syncthreads();   // all compute + async writes done before overlaying stage region
    {
        const int col0 = wn * 32;
#pragma unroll
        for (int mf = 0; mf < 4; mf++) {
            int r = wm * 64 + mf * 16 + qr;
#pragma unroll
            for (int nf = 0; nf < 4; nf++) {
                int cL = col0 + nf * 8 + 2 * qc;
                *(float2*)&smf[r * EPI_STRIDE + cL] = make_float2(acc[mf][nf][0], acc[mf][nf][1]);
                *(float2*)&smf[(r + 8) * EPI_STRIDE + cL] = make_float2(acc[mf][nf][2], acc[mf][nf][3]);
            }
        }
    }
    __syncthreads();

    {
        const int hl = tid & 31;          // h within block
        const int rg = tid >> 5;          // 0..7
        float4 bv = *(float4*)&smf[OFF_BIAS / 4 + hl * 4];
        const int h = hb + hl;
#pragma unroll 1
        for (int i = 0; i < 16; i++) {
            int r = i * 8 + rg;
            float4 gt = *(float4*)&smf[r * EPI_STRIDE + hl * 4];
            size_t oidx = (size_t)(m_base + r) * HH + h;
            float cc = cin[oidx];
            float ig = fast_sigmoid(gt.x + bv.x);
            float fg = fast_sigmoid(gt.y + bv.y);
            float g2 = fast_tanh(gt.z + bv.z);
            float og = fast_sigmoid(gt.w + bv.w);
            float nc = fg * cc + ig * g2;
            float nh = og * fast_tanh(nc);
            out[oidx] = nh;
            out[oidx + (size_t)BB * HH] = nh;
            out[oidx + 2 * (size_t)BB * HH] = nc;
        }
    }
}

// ================= launch =================
extern "C" void kernel_launch(void* const* d_in, const int* in_sizes, int n_in,
                              void* d_out, int out_size) {
    const float* X  = (const float*)d_in[0];
    const float* Hs = (const float*)d_in[1];
    const float* c  = (const float*)d_in[2];
    const float* Wx = (const float*)d_in[3];
    const float* Wh = (const float*)d_in[4];
    const float* bx = (const float*)d_in[5];
    const float* bh = (const float*)d_in[6];
    float* out = (float*)d_out;

    cudaFuncSetAttribute(lstm_gemm, cudaFuncAttributeMaxDynamicSharedMemorySize, SMEM_TOTAL);

    convert_AB<<<A_BLOCKS + B_BLOCKS, 256>>>(X, Hs, Wx, Wh, bx, bh);
    lstm_gemm<<<dim3(NNI / BN, BB / BM), THREADS, SMEM_TOTAL>>>(c, out);
}

// round 13
// speedup vs baseline: 1.0264x; 1.0264x over previous
#include <cuda_runtime.h>
#include <cuda_fp16.h>
#include <cstdint>
#include <cstddef>

// ---------------- problem dims ----------------
#define BB 8192
#define HH 1024
#define KTOT 2048            // concat K = I + H
#define NNI 4096             // interleaved gate dim n' = 4*h + g

// ---------------- GEMM tiling ----------------
#define BM 128
#define BN 64
#define THREADS 256                  // 8 warps: 4 (M) x 2 (N), warp tile 32x32
#define NSTAGES 3
#define KITERS2 32                   // mainloop iterations, 64 K each
#define SUB_A_U4 512                 // 32-K A subtile (128 rows) in uint4
#define SUB_B_U4 256                 // 32-K B subtile (64 rows) in uint4
#define A_TILE_U4 (2 * SUB_A_U4)     // 64-K stage A = 16KB
#define B_TILE_U4 (2 * SUB_B_U4)     // 8KB
#define A_BYTES (A_TILE_U4 * 16)     // 16384
#define B_BYTES (B_TILE_U4 * 16)     // 8192
#define STAGE_BYTES (A_BYTES + B_BYTES)        // 24576
#define STAGE_REGION (NSTAGES * STAGE_BYTES)   // 73728
#define EPI_STRIDE 68                // 64 + 4 pad floats per epilogue row
#define EPI_BYTES (BM * EPI_STRIDE * 4)        // 34816 (overlays stage region)
#define OFF_BIAS STAGE_REGION
#define SMEM_TOTAL (STAGE_REGION + 512)        // 74240 -> 3 CTAs/SM

// ---------------- scratch: fragment-ordered fp16 operands ----------------
// g_A: [mb(64)][kt32(64)][m16(8)][ks(2)][lane(32)] x uint4
//      uint4 = {h2(A[R][C..]), h2(A[R+8][C..]), h2(A[R][C+8..]), h2(A[R+8][C+8..])}
__device__ uint4 g_A[(size_t)BB * KTOT / 8];
// g_B: [nb(64)][kt32(64)][pu(4)][ks(2)][lane(32)] x uint4
//      uint4 = {h2(B[N0][C..]), h2(B[N0][C+8..]), h2(B[N1][C..]), h2(B[N1][C+8..])},
//      N0 = nb*64 + pu*16 + qr, N1 = N0+8
__device__ uint4 g_B[(size_t)NNI * KTOT / 8];
__device__ float g_bias[NNI];   // interleaved 4h+g

// ---------------- helpers ----------------
__device__ __forceinline__ void cpa16(uint32_t s, const void* g) {
    asm volatile("cp.async.cg.shared.global [%0], [%1], 16;" :: "r"(s), "l"(g));
}

__device__ __forceinline__ uint32_t h2pack(float lo, float hi) {
    __half2 h = __floats2half2_rn(lo, hi);
    return *reinterpret_cast<uint32_t*>(&h);
}

__device__ __forceinline__ void mma_f16(float* d, const uint4& a, uint32_t b0, uint32_t b1) {
    asm volatile(
        "mma.sync.aligned.m16n8k16.row.col.f32.f16.f16.f32 "
        "{%0,%1,%2,%3}, {%4,%5,%6,%7}, {%8,%9}, {%0,%1,%2,%3};"
        : "+f"(d[0]), "+f"(d[1]), "+f"(d[2]), "+f"(d[3])
        : "r"(a.x), "r"(a.y), "r"(a.z), "r"(a.w), "r"(b0), "r"(b1));
}

__device__ __forceinline__ float fast_sigmoid(float x) {
    return __fdividef(1.0f, 1.0f + __expf(-x));
}
__device__ __forceinline__ float fast_tanh(float x) {
    return __fmaf_rn(2.0f, __fdividef(1.0f, 1.0f + __expf(-2.0f * x)), -1.0f);
}

// ================= pre-pass (merged): fp16-round + concat + fragment-order =================
#define A_BLOCKS 8192   // 2^21 uint4 / 256
#define B_BLOCKS 4096   // 2^20 uint4 / 256

__global__ __launch_bounds__(256) void convert_AB(const float* __restrict__ X,
                                                  const float* __restrict__ Hs,
                                                  const float* __restrict__ Wx,
                                                  const float* __restrict__ Wh,
                                                  const float* __restrict__ bx,
                                                  const float* __restrict__ bh) {
    if (blockIdx.x < A_BLOCKS) {
        size_t idx = (size_t)blockIdx.x * 256 + threadIdx.x;
        int lane = (int)(idx & 31);
        int ks   = (int)((idx >> 5) & 1);
        int m16  = (int)((idx >> 6) & 7);
        int kt   = (int)((idx >> 9) & 63);
        int mb   = (int)(idx >> 15);
        int qr = lane >> 2, qc = lane & 3;
        int R = mb * 128 + m16 * 16 + qr;
        int C = kt * 32 + ks * 16 + 2 * qc;

        const float* src = (C < 1024) ? X : Hs;
        int c0 = C & 1023;
        float2 r0a = *(const float2*)&src[(size_t)R * 1024 + c0];
        float2 r0b = *(const float2*)&src[(size_t)R * 1024 + c0 + 8];
        float2 r1a = *(const float2*)&src[(size_t)(R + 8) * 1024 + c0];
        float2 r1b = *(const float2*)&src[(size_t)(R + 8) * 1024 + c0 + 8];

        uint4 o;
        o.x = h2pack(r0a.x, r0a.y);
        o.y = h2pack(r1a.x, r1a.y);
        o.z = h2pack(r0b.x, r0b.y);
        o.w = h2pack(r1b.x, r1b.y);
        g_A[idx] = o;
    } else {
        size_t idx = (size_t)(blockIdx.x - A_BLOCKS) * 256 + threadIdx.x;
        int lane = (int)(idx & 31);
        int ks   = (int)((idx >> 5) & 1);
        int pu   = (int)((idx >> 6) & 3);
        int kt   = (int)((idx >> 8) & 63);
        int nb   = (int)(idx >> 14);
        int qr = lane >> 2, qc = lane & 3;
        int C = kt * 32 + ks * 16 + 2 * qc;
        int N0 = nb * 64 + pu * 16 + qr;
        int N1 = N0 + 8;
        int sr0 = (N0 & 3) * 1024 + (N0 >> 2);    // n' = 4h+g -> row g*1024+h
        int sr1 = (N1 & 3) * 1024 + (N1 >> 2);

        const float* src = (C < 1024) ? Wx : Wh;
        int c0 = C & 1023;
        float2 w0a = *(const float2*)&src[(size_t)sr0 * 1024 + c0];
        float2 w0b = *(const float2*)&src[(size_t)sr0 * 1024 + c0 + 8];
        float2 w1a = *(const float2*)&src[(size_t)sr1 * 1024 + c0];
        float2 w1b = *(const float2*)&src[(size_t)sr1 * 1024 + c0 + 8];

        uint4 o;
        o.x = h2pack(w0a.x, w0a.y);
        o.y = h2pack(w0b.x, w0b.y);
        o.z = h2pack(w1a.x, w1a.y);
        o.w = h2pack(w1b.x, w1b.y);
        g_B[idx] = o;

        if (kt == 0 && ks == 0 && qc == 0) {
            g_bias[N0] = bx[sr0] + bh[sr0];
            g_bias[N1] = bx[sr1] + bh[sr1];
        }
    }
}

// ================= fused GEMM + LSTM epilogue (3 CTAs/SM, 8 warps) =================
__global__ __launch_bounds__(THREADS, 3) void lstm_gemm(const float* __restrict__ cin,
                                                        float* __restrict__ out) {
    extern __shared__ char smem[];
    float* smf = (float*)smem;
    const int tid  = threadIdx.x;
    const int lane = tid & 31;
    const int wid  = tid >> 5;
    const int wm   = wid >> 1;      // 4 warps over M (32 rows each)
    const int wn   = wid & 1;       // 2 warps over N (32 cols each)
    const int qr   = lane >> 2;
    const int qc   = lane & 3;

    const int mb = blockIdx.y;      // 0..63
    const int nb = blockIdx.x;      // 0..63
    const int m_base = mb * BM;
    const int hb = nb * 16;         // 16 h values per CTA

    uint32_t sb;
    asm("{ .reg .u64 t; cvta.to.shared.u64 t, %1; cvt.u32.u64 %0, t; }" : "=r"(sb) : "l"(smem));

    if (tid < 64) smf[OFF_BIAS / 4 + tid] = g_bias[nb * 64 + tid];

    float acc[2][4][4] = {};   // 2 m16-frags x 4 n8-frags

    const uint4* gA4 = g_A + ((size_t)mb * 64) * SUB_A_U4;
    const uint4* gB4 = g_B + ((size_t)nb * 64) * SUB_B_U4;

    // ---- prologue: fill stages 0..1 (1536 chunks / 256 threads = 6 each) ----
#pragma unroll
    for (int s = 0; s < NSTAGES - 1; s++) {
        uint32_t base = sb + (uint32_t)s * STAGE_BYTES;
        const uint4* a_src = gA4 + (size_t)s * A_TILE_U4;
        const uint4* b_src = gB4 + (size_t)s * B_TILE_U4;
#pragma unroll
        for (int j = 0; j < 4; j++) {
            int ch = j * THREADS + tid;
            cpa16(base + (uint32_t)ch * 16u, a_src + ch);
        }
#pragma unroll
        for (int j = 0; j < 2; j++) {
            int ch = j * THREADS + tid;
            cpa16(base + (uint32_t)(A_BYTES + ch * 16), b_src + ch);
        }
        asm volatile("cp.async.commit_group;");
    }

#pragma unroll 1
    for (int it = 0; it < KITERS2; ++it) {
        asm volatile("cp.async.wait_group %0;" :: "n"(NSTAGES - 2));
        __syncthreads();

        if (it + NSTAGES - 1 < KITERS2) {
            const int ns = (it + NSTAGES - 1) % NSTAGES;
            uint32_t base = sb + (uint32_t)ns * STAGE_BYTES;
            const uint4* a_src = gA4 + (size_t)(it + NSTAGES - 1) * A_TILE_U4;
            const uint4* b_src = gB4 + (size_t)(it + NSTAGES - 1) * B_TILE_U4;
#pragma unroll
            for (int j = 0; j < 4; j++) {
                int ch = j * THREADS + tid;
                cpa16(base + (uint32_t)ch * 16u, a_src + ch);
            }
#pragma unroll
            for (int j = 0; j < 2; j++) {
                int ch = j * THREADS + tid;
                cpa16(base + (uint32_t)(A_BYTES + ch * 16), b_src + ch);
            }
        }
        asm volatile("cp.async.commit_group;");   // empty commit in tail keeps count

        const int cur = it % NSTAGES;
        const uint4* sA = (const uint4*)(smem + cur * STAGE_BYTES) + lane;
        const uint4* sB = (const uint4*)(smem + cur * STAGE_BYTES + A_BYTES) + lane;

#pragma unroll
        for (int ks2 = 0; ks2 < 4; ks2++) {       // 4 x 16-K steps per iteration
            const int aoff = (ks2 >> 1) * SUB_A_U4 + (ks2 & 1) * 32;
            const int boff = (ks2 >> 1) * SUB_B_U4 + (ks2 & 1) * 32;
            uint4 a0 = sA[aoff + ((wm * 2 + 0) * 2) * 32];
            uint4 a1 = sA[aoff + ((wm * 2 + 1) * 2) * 32];
            uint4 b0 = sB[boff + ((wn * 2 + 0) * 2) * 32];
            uint4 b1 = sB[boff + ((wn * 2 + 1) * 2) * 32];
#pragma unroll
            for (int mf = 0; mf < 2; mf++) {
                const uint4& a = (mf == 0) ? a0 : a1;
                mma_f16(acc[mf][0], a, b0.x, b0.y);
                mma_f16(acc[mf][1], a, b0.z, b0.w);
                mma_f16(acc[mf][2], a, b1.x, b1.y);
                mma_f16(acc[mf][3], a, b1.z, b1.w);
            }
        }
    }

    // ---------------- fused epilogue ----------------
    asm volatile("cp.async.wait_group 0;");
    __syncthreads();   // all compute + async writes done before overlaying stage region
    {
        const int col0 = wn * 32;
#pragma unroll
        for (int mf = 0; mf < 2; mf++) {
            int r = wm * 32 + mf * 16 + qr;
#pragma unroll
            for (int nf = 0; nf < 4; nf++) {
                int cL = col0 + nf * 8 + 2 * qc;
                *(float2*)&smf[r * EPI_STRIDE + cL] = make_float2(acc[mf][nf][0], acc[mf][nf][1]);
                *(float2*)&smf[(r + 8) * EPI_STRIDE + cL] = make_float2(acc[mf][nf][2], acc[mf][nf][3]);
            }
        }
    }
    __syncthreads();

    {
        const int hl = tid & 15;          // h within block (0..15)
        const int rg = tid >> 4;          // 0..15
        float4 bv = *(float4*)&smf[OFF_BIAS / 4 + hl * 4];
        const int h = hb + hl;
#pragma unroll 1
        for (int i = 0; i < 8; i++) {
            int r = i * 16 + rg;
            float4 gt = *(float4*)&smf[r * EPI_STRIDE + hl * 4];
            size_t oidx = (size_t)(m_base + r) * HH + h;
            float cc = cin[oidx];
            float ig = fast_sigmoid(gt.x + bv.x);
            float fg = fast_sigmoid(gt.y + bv.y);
            float g2 = fast_tanh(gt.z + bv.z);
            float og = fast_sigmoid(gt.w + bv.w);
            float nc = fg * cc + ig * g2;
            float nh = og * fast_tanh(nc);
            out[oidx] = nh;
            out[oidx + (size_t)BB * HH] = nh;
            out[oidx + 2 * (size_t)BB * HH] = nc;
        }
    }
}

// ================= launch =================
extern "C" void kernel_launch(void* const* d_in, const int* in_sizes, int n_in,
                              void* d_out, int out_size) {
    const float* X  = (const float*)d_in[0];
    const float* Hs = (const float*)d_in[1];
    const float* c  = (const float*)d_in[2];
    const float* Wx = (const float*)d_in[3];
    const float* Wh = (const float*)d_in[4];
    const float* bx = (const float*)d_in[5];
    const float* bh = (const float*)d_in[6];
    float* out = (float*)d_out;

    cudaFuncSetAttribute(lstm_gemm, cudaFuncAttributeMaxDynamicSharedMemorySize, SMEM_TOTAL);

    convert_AB<<<A_BLOCKS + B_BLOCKS, 256>>>(X, Hs, Wx, Wh, bx, bh);
    lstm_gemm<<<dim3(NNI / BN, BB / BM), THREADS, SMEM_TOTAL>>>(c, out);
}

// round 14
// speedup vs baseline: 1.0712x; 1.0436x over previous
#include <cuda_runtime.h>
#include <cuda_fp16.h>
#include <cstdint>
#include <cstddef>

// ---------------- problem dims ----------------
#define BB 8192
#define HH 1024
#define KTOT 2048            // concat K = I + H
#define NNI 4096             // interleaved gate dim n' = 4*h + g

// ---------------- GEMM tiling ----------------
#define BM 128
#define BN 64
#define THREADS 256                  // 8 warps: 4 (M) x 2 (N), warp tile 32x32
#define NSTAGES 3
#define KITERS2 32                   // mainloop iterations, 64 K each
#define SUB_A_U4 512                 // 32-K A subtile (128 rows) in uint4
#define SUB_B_U4 256                 // 32-K B subtile (64 rows) in uint4
#define A_TILE_U4 (2 * SUB_A_U4)     // 64-K stage A = 16KB
#define B_TILE_U4 (2 * SUB_B_U4)     // 8KB
#define A_BYTES (A_TILE_U4 * 16)     // 16384
#define B_BYTES (B_TILE_U4 * 16)     // 8192
#define STAGE_BYTES (A_BYTES + B_BYTES)        // 24576
#define STAGE_REGION (NSTAGES * STAGE_BYTES)   // 73728
#define EPI_STRIDE 68                // 64 + 4 pad floats per epilogue row
#define EPI_BYTES (BM * EPI_STRIDE * 4)        // 34816 (overlays stage region)
#define OFF_BIAS STAGE_REGION                  // 256 B of bias
#define OFF_FULL (STAGE_REGION + 256)          // 3 x 8B full barriers
#define OFF_EMPTY (STAGE_REGION + 256 + 24)    // 3 x 8B empty barriers
#define SMEM_TOTAL (STAGE_REGION + 512)        // 74240 -> 3 CTAs/SM

// ---------------- scratch: fragment-ordered fp16 operands ----------------
// g_A: [mb(64)][kt32(64)][m16(8)][ks(2)][lane(32)] x uint4
__device__ uint4 g_A[(size_t)BB * KTOT / 8];
// g_B: [nb(64)][kt32(64)][pu(4)][ks(2)][lane(32)] x uint4
__device__ uint4 g_B[(size_t)NNI * KTOT / 8];
__device__ float g_bias[NNI];   // interleaved 4h+g

// ---------------- helpers ----------------
__device__ __forceinline__ void cpa16(uint32_t s, const void* g) {
    asm volatile("cp.async.cg.shared.global [%0], [%1], 16;" :: "r"(s), "l"(g));
}

__device__ __forceinline__ uint32_t h2pack(float lo, float hi) {
    __half2 h = __floats2half2_rn(lo, hi);
    return *reinterpret_cast<uint32_t*>(&h);
}

__device__ __forceinline__ void mma_f16(float* d, const uint4& a, uint32_t b0, uint32_t b1) {
    asm volatile(
        "mma.sync.aligned.m16n8k16.row.col.f32.f16.f16.f32 "
        "{%0,%1,%2,%3}, {%4,%5,%6,%7}, {%8,%9}, {%0,%1,%2,%3};"
        : "+f"(d[0]), "+f"(d[1]), "+f"(d[2]), "+f"(d[3])
        : "r"(a.x), "r"(a.y), "r"(a.z), "r"(a.w), "r"(b0), "r"(b1));
}

__device__ __forceinline__ float fast_sigmoid(float x) {
    return __fdividef(1.0f, 1.0f + __expf(-x));
}
__device__ __forceinline__ float fast_tanh(float x) {
    return __fmaf_rn(2.0f, __fdividef(1.0f, 1.0f + __expf(-2.0f * x)), -1.0f);
}

#define MBARRIER_INIT(addr, cnt) \
    asm volatile("mbarrier.init.shared.b64 [%0], %1;" :: "r"((uint32_t)(addr)), "r"((uint32_t)(cnt)) : "memory")

#define MBARRIER_ARRIVE(addr) \
    asm volatile("mbarrier.arrive.release.cta.shared::cta.b64 _, [%0];" :: "r"((uint32_t)(addr)) : "memory")

#define CPASYNC_ARRIVE(addr) \
    asm volatile("cp.async.mbarrier.arrive.noinc.shared::cta.b64 [%0];" :: "r"((uint32_t)(addr)) : "memory")

#define MBARRIER_WAIT(addr, par) do {                                              \
    uint32_t _m = (uint32_t)(addr); uint32_t _p = (uint32_t)(par); uint32_t _d;    \
    asm volatile("{\n\t.reg .pred p;\n\t"                                          \
        "mbarrier.try_wait.parity.acquire.cta.shared::cta.b64 p, [%1], %2;\n\t"    \
        "selp.b32 %0, 1, 0, p;\n\t}"                                               \
        : "=r"(_d) : "r"(_m), "r"(_p) : "memory");                                 \
    if (!_d) {                                                                     \
        asm volatile("{\n\t.reg .pred P1;\n\t"                                     \
            "W%=:\n\t"                                                             \
            "mbarrier.try_wait.parity.acquire.cta.shared::cta.b64 P1, [%0], %1, 0x989680;\n\t" \
            "@P1 bra.uni D%=;\n\t bra.uni W%=;\n\t D%=:\n\t}"                      \
            :: "r"(_m), "r"(_p) : "memory");                                       \
    } } while (0)

// ================= pre-pass (merged): fp16-round + concat + fragment-order =================
#define A_BLOCKS 8192   // 2^21 uint4 / 256
#define B_BLOCKS 4096   // 2^20 uint4 / 256

__global__ __launch_bounds__(256) void convert_AB(const float* __restrict__ X,
                                                  const float* __restrict__ Hs,
                                                  const float* __restrict__ Wx,
                                                  const float* __restrict__ Wh,
                                                  const float* __restrict__ bx,
                                                  const float* __restrict__ bh) {
    if (blockIdx.x < A_BLOCKS) {
        size_t idx = (size_t)blockIdx.x * 256 + threadIdx.x;
        int lane = (int)(idx & 31);
        int ks   = (int)((idx >> 5) & 1);
        int m16  = (int)((idx >> 6) & 7);
        int kt   = (int)((idx >> 9) & 63);
        int mb   = (int)(idx >> 15);
        int qr = lane >> 2, qc = lane & 3;
        int R = mb * 128 + m16 * 16 + qr;
        int C = kt * 32 + ks * 16 + 2 * qc;

        const float* src = (C < 1024) ? X : Hs;
        int c0 = C & 1023;
        float2 r0a = *(const float2*)&src[(size_t)R * 1024 + c0];
        float2 r0b = *(const float2*)&src[(size_t)R * 1024 + c0 + 8];
        float2 r1a = *(const float2*)&src[(size_t)(R + 8) * 1024 + c0];
        float2 r1b = *(const float2*)&src[(size_t)(R + 8) * 1024 + c0 + 8];

        uint4 o;
        o.x = h2pack(r0a.x, r0a.y);
        o.y = h2pack(r1a.x, r1a.y);
        o.z = h2pack(r0b.x, r0b.y);
        o.w = h2pack(r1b.x, r1b.y);
        g_A[idx] = o;
    } else {
        size_t idx = (size_t)(blockIdx.x - A_BLOCKS) * 256 + threadIdx.x;
        int lane = (int)(idx & 31);
        int ks   = (int)((idx >> 5) & 1);
        int pu   = (int)((idx >> 6) & 3);
        int kt   = (int)((idx >> 8) & 63);
        int nb   = (int)(idx >> 14);
        int qr = lane >> 2, qc = lane & 3;
        int C = kt * 32 + ks * 16 + 2 * qc;
        int N0 = nb * 64 + pu * 16 + qr;
        int N1 = N0 + 8;
        int sr0 = (N0 & 3) * 1024 + (N0 >> 2);    // n' = 4h+g -> row g*1024+h
        int sr1 = (N1 & 3) * 1024 + (N1 >> 2);

        const float* src = (C < 1024) ? Wx : Wh;
        int c0 = C & 1023;
        float2 w0a = *(const float2*)&src[(size_t)sr0 * 1024 + c0];
        float2 w0b = *(const float2*)&src[(size_t)sr0 * 1024 + c0 + 8];
        float2 w1a = *(const float2*)&src[(size_t)sr1 * 1024 + c0];
        float2 w1b = *(const float2*)&src[(size_t)sr1 * 1024 + c0 + 8];

        uint4 o;
        o.x = h2pack(w0a.x, w0a.y);
        o.y = h2pack(w0b.x, w0b.y);
        o.z = h2pack(w1a.x, w1a.y);
        o.w = h2pack(w1b.x, w1b.y);
        g_B[idx] = o;

        if (kt == 0 && ks == 0 && qc == 0) {
            g_bias[N0] = bx[sr0] + bh[sr0];
            g_bias[N1] = bx[sr1] + bh[sr1];
        }
    }
}

// ================= fused GEMM + LSTM epilogue (3 CTAs/SM, mbarrier pipeline) =================
__global__ __launch_bounds__(THREADS, 3) void lstm_gemm(const float* __restrict__ cin,
                                                        float* __restrict__ out) {
    extern __shared__ char smem[];
    float* smf = (float*)smem;
    const int tid  = threadIdx.x;
    const int lane = tid & 31;
    const int wid  = tid >> 5;
    const int wm   = wid >> 1;      // 4 warps over M (32 rows each)
    const int wn   = wid & 1;       // 2 warps over N (32 cols each)
    const int qr   = lane >> 2;
    const int qc   = lane & 3;

    const int mb = blockIdx.y;      // 0..63
    const int nb = blockIdx.x;      // 0..63
    const int m_base = mb * BM;
    const int hb = nb * 16;         // 16 h values per CTA

    uint32_t sb;
    asm("{ .reg .u64 t; cvta.to.shared.u64 t, %1; cvt.u32.u64 %0, t; }" : "=r"(sb) : "l"(smem));

    if (tid < 64) smf[OFF_BIAS / 4 + tid] = g_bias[nb * 64 + tid];
    if (tid == 0) {
#pragma unroll
        for (int s = 0; s < NSTAGES; s++) {
            MBARRIER_INIT(sb + OFF_FULL + 8 * s, THREADS);
            MBARRIER_INIT(sb + OFF_EMPTY + 8 * s, THREADS);
        }
    }
    __syncthreads();   // barriers initialized before any arrive

    float acc[2][4][4] = {};   // 2 m16-frags x 4 n8-frags

    const uint4* gA4 = g_A + ((size_t)mb * 64) * SUB_A_U4;
    const uint4* gB4 = g_B + ((size_t)nb * 64) * SUB_B_U4;

    // ---- prologue: produce tiles 0,1 into stages 0,1 (no empty wait needed) ----
#pragma unroll
    for (int s = 0; s < NSTAGES - 1; s++) {
        uint32_t base = sb + (uint32_t)s * STAGE_BYTES;
        const uint4* a_src = gA4 + (size_t)s * A_TILE_U4;
        const uint4* b_src = gB4 + (size_t)s * B_TILE_U4;
#pragma unroll
        for (int j = 0; j < 4; j++) {
            int ch = j * THREADS + tid;
            cpa16(base + (uint32_t)ch * 16u, a_src + ch);
        }
#pragma unroll
        for (int j = 0; j < 2; j++) {
            int ch = j * THREADS + tid;
            cpa16(base + (uint32_t)(A_BYTES + ch * 16), b_src + ch);
        }
        CPASYNC_ARRIVE(sb + OFF_FULL + 8 * s);
    }

#pragma unroll 1
    for (int it = 0; it < KITERS2; ++it) {
        // ---- produce tile j = it+2 into stage j%3 ----
        const int j = it + NSTAGES - 1;
        if (j < KITERS2) {
            const int s2 = j % NSTAGES;
            if (j >= NSTAGES) {
                // stage s2 last consumed at iteration j-3; wait for that consume epoch
                MBARRIER_WAIT(sb + OFF_EMPTY + 8 * s2, ((j / NSTAGES) - 1) & 1);
            }
            uint32_t base = sb + (uint32_t)s2 * STAGE_BYTES;
            const uint4* a_src = gA4 + (size_t)j * A_TILE_U4;
            const uint4* b_src = gB4 + (size_t)j * B_TILE_U4;
#pragma unroll
            for (int jj = 0; jj < 4; jj++) {
                int ch = jj * THREADS + tid;
                cpa16(base + (uint32_t)ch * 16u, a_src + ch);
            }
#pragma unroll
            for (int jj = 0; jj < 2; jj++) {
                int ch = jj * THREADS + tid;
                cpa16(base + (uint32_t)(A_BYTES + ch * 16), b_src + ch);
            }
            CPASYNC_ARRIVE(sb + OFF_FULL + 8 * s2);
        }

        // ---- consume stage it%3 ----
        const int cur = it % NSTAGES;
        MBARRIER_WAIT(sb + OFF_FULL + 8 * cur, (it / NSTAGES) & 1);

        const uint4* sA = (const uint4*)(smem + cur * STAGE_BYTES) + lane;
        const uint4* sB = (const uint4*)(smem + cur * STAGE_BYTES + A_BYTES) + lane;

#pragma unroll
        for (int ks2 = 0; ks2 < 4; ks2++) {       // 4 x 16-K steps per iteration
            const int aoff = (ks2 >> 1) * SUB_A_U4 + (ks2 & 1) * 32;
            const int boff = (ks2 >> 1) * SUB_B_U4 + (ks2 & 1) * 32;
            uint4 a0 = sA[aoff + ((wm * 2 + 0) * 2) * 32];
            uint4 a1 = sA[aoff + ((wm * 2 + 1) * 2) * 32];
            uint4 b0 = sB[boff + ((wn * 2 + 0) * 2) * 32];
            uint4 b1 = sB[boff + ((wn * 2 + 1) * 2) * 32];
#pragma unroll
            for (int mf = 0; mf < 2; mf++) {
                const uint4& a = (mf == 0) ? a0 : a1;
                mma_f16(acc[mf][0], a, b0.x, b0.y);
                mma_f16(acc[mf][1], a, b0.z, b0.w);
                mma_f16(acc[mf][2], a, b1.x, b1.y);
                mma_f16(acc[mf][3], a, b1.z, b1.w);
            }
        }

        MBARRIER_ARRIVE(sb + OFF_EMPTY + 8 * cur);   // done reading this stage
    }

    // ---------------- fused epilogue ----------------
    __syncthreads();   // all warps done computing before overlaying stage region
    {
        const int col0 = wn * 32;
#pragma unroll
        for (int mf = 0; mf < 2; mf++) {
            int r = wm * 32 + mf * 16 + qr;
#pragma unroll
            for (int nf = 0; nf < 4; nf++) {
                int cL = col0 + nf * 8 + 2 * qc;
                *(float2*)&smf[r * EPI_STRIDE + cL] = make_float2(acc[mf][nf][0], acc[mf][nf][1]);
                *(float2*)&smf[(r + 8) * EPI_STRIDE + cL] = make_float2(acc[mf][nf][2], acc[mf][nf][3]);
            }
        }
    }
    __syncthreads();

    {
        const int hl = tid & 15;          // h within block (0..15)
        const int rg = tid >> 4;          // 0..15
        float4 bv = *(float4*)&smf[OFF_BIAS / 4 + hl * 4];
        const int h = hb + hl;
#pragma unroll 1
        for (int i = 0; i < 8; i++) {
            int r = i * 16 + rg;
            float4 gt = *(float4*)&smf[r * EPI_STRIDE + hl * 4];
            size_t oidx = (size_t)(m_base + r) * HH + h;
            float cc = cin[oidx];
            float ig = fast_sigmoid(gt.x + bv.x);
            float fg = fast_sigmoid(gt.y + bv.y);
            float g2 = fast_tanh(gt.z + bv.z);
            float og = fast_sigmoid(gt.w + bv.w);
            float nc = fg * cc + ig * g2;
            float nh = og * fast_tanh(nc);
            out[oidx] = nh;
            out[oidx + (size_t)BB * HH] = nh;
            out[oidx + 2 * (size_t)BB * HH] = nc;
        }
    }
}

// ================= launch =================
extern "C" void kernel_launch(void* const* d_in, const int* in_sizes, int n_in,
                              void* d_out, int out_size) {
    const float* X  = (const float*)d_in[0];
    const float* Hs = (const float*)d_in[1];
    const float* c  = (const float*)d_in[2];
    const float* Wx = (const float*)d_in[3];
    const float* Wh = (const float*)d_in[4];
    const float* bx = (const float*)d_in[5];
    const float* bh = (const float*)d_in[6];
    float* out = (float*)d_out;

    cudaFuncSetAttribute(lstm_gemm, cudaFuncAttributeMaxDynamicSharedMemorySize, SMEM_TOTAL);

    convert_AB<<<A_BLOCKS + B_BLOCKS, 256>>>(X, Hs, Wx, Wh, bx, bh);
    lstm_gemm<<<dim3(NNI / BN, BB / BM), THREADS, SMEM_TOTAL>>>(c, out);
}

// round 16
// speedup vs baseline: 1.0960x; 1.0231x over previous
#include <cuda_runtime.h>
#include <cuda_fp16.h>
#include <cstdint>
#include <cstddef>

// ---------------- problem dims ----------------
#define BB 8192
#define HH 1024
#define KTOT 2048            // concat K = I + H
#define NNI 4096             // interleaved gate dim n' = 4*h + g

// ---------------- GEMM tiling ----------------
#define BM 128
#define BN 128
#define THREADS 256                  // 8 warps: 2 (M) x 4 (N), warp tile 64x32
#define NSTAGES 3
#define KITERS2 32                   // mainloop iterations, 64 K each
#define SUB_A_U4 512                 // 32-K subtile (128 rows) in uint4
#define SUB_B_U4 512
#define A_TILE_U4 (2 * SUB_A_U4)     // 64-K stage A = 16KB
#define B_TILE_U4 (2 * SUB_B_U4)
#define A_BYTES (A_TILE_U4 * 16)     // 16384
#define B_BYTES (B_TILE_U4 * 16)     // 16384
#define STAGE_BYTES (A_BYTES + B_BYTES)        // 32768
#define STAGE_REGION (NSTAGES * STAGE_BYTES)   // 98304
#define EPI_STRIDE 132               // 128 + 4 pad floats per epilogue row
#define EPI_BYTES (BM * EPI_STRIDE * 4)        // 67584 (overlays stage region)
#define OFF_BIAS STAGE_REGION                  // 512 B of bias
#define OFF_FULL (STAGE_REGION + 512)          // 3 x 8B full barriers
#define OFF_EMPTY (STAGE_REGION + 512 + 24)    // 3 x 8B empty barriers
#define SMEM_TOTAL (STAGE_REGION + 1024)       // 99328 -> 2 CTAs/SM

// ---------------- scratch: fragment-ordered fp16 operands ----------------
// g_A: [mb(64)][kt32(64)][m16(8)][ks(2)][lane(32)] x uint4
//      uint4 = {h2(A[R][C..]), h2(A[R+8][C..]), h2(A[R][C+8..]), h2(A[R+8][C+8..])}
__device__ uint4 g_A[(size_t)BB * KTOT / 8];
// g_B: [nb(32)][kt32(64)][wn(4)][p(2)][ks(2)][lane(32)] x uint4
//      uint4 = {h2(B[N0][C..]), h2(B[N0][C+8..]), h2(B[N1][C..]), h2(B[N1][C+8..])},
//      N0 = nb*128 + wn*32 + p*16 + qr, N1 = N0+8
__device__ uint4 g_B[(size_t)NNI * KTOT / 8];
__device__ float g_bias[NNI];   // interleaved 4h+g

// ---------------- helpers ----------------
__device__ __forceinline__ void cpa16(uint32_t s, const void* g) {
    asm volatile("cp.async.cg.shared.global [%0], [%1], 16;" :: "r"(s), "l"(g));
}

__device__ __forceinline__ uint32_t h2pack(float lo, float hi) {
    __half2 h = __floats2half2_rn(lo, hi);
    return *reinterpret_cast<uint32_t*>(&h);
}

__device__ __forceinline__ void mma_f16(float* d, const uint4& a, uint32_t b0, uint32_t b1) {
    asm volatile(
        "mma.sync.aligned.m16n8k16.row.col.f32.f16.f16.f32 "
        "{%0,%1,%2,%3}, {%4,%5,%6,%7}, {%8,%9}, {%0,%1,%2,%3};"
        : "+f"(d[0]), "+f"(d[1]), "+f"(d[2]), "+f"(d[3])
        : "r"(a.x), "r"(a.y), "r"(a.z), "r"(a.w), "r"(b0), "r"(b1));
}

__device__ __forceinline__ float fast_sigmoid(float x) {
    return __fdividef(1.0f, 1.0f + __expf(-x));
}
__device__ __forceinline__ float fast_tanh(float x) {
    return __fmaf_rn(2.0f, __fdividef(1.0f, 1.0f + __expf(-2.0f * x)), -1.0f);
}

#define MBARRIER_INIT(addr, cnt) \
    asm volatile("mbarrier.init.shared.b64 [%0], %1;" :: "r"((uint32_t)(addr)), "r"((uint32_t)(cnt)) : "memory")

#define MBARRIER_ARRIVE(addr) \
    asm volatile("mbarrier.arrive.release.cta.shared::cta.b64 _, [%0];" :: "r"((uint32_t)(addr)) : "memory")

#define CPASYNC_ARRIVE(addr) \
    asm volatile("cp.async.mbarrier.arrive.noinc.shared::cta.b64 [%0];" :: "r"((uint32_t)(addr)) : "memory")

#define MBARRIER_WAIT(addr, par) do {                                              \
    uint32_t _m = (uint32_t)(addr); uint32_t _p = (uint32_t)(par); uint32_t _d;    \
    asm volatile("{\n\t.reg .pred p;\n\t"                                          \
        "mbarrier.try_wait.parity.acquire.cta.shared::cta.b64 p, [%1], %2;\n\t"    \
        "selp.b32 %0, 1, 0, p;\n\t}"                                               \
        : "=r"(_d) : "r"(_m), "r"(_p) : "memory");                                 \
    if (!_d) {                                                                     \
        asm volatile("{\n\t.reg .pred P1;\n\t"                                     \
            "W%=:\n\t"                                                             \
            "mbarrier.try_wait.parity.acquire.cta.shared::cta.b64 P1, [%0], %1, 0x989680;\n\t" \
            "@P1 bra.uni D%=;\n\t bra.uni W%=;\n\t D%=:\n\t}"                      \
            :: "r"(_m), "r"(_p) : "memory");                                       \
    } } while (0)

// ================= pre-pass (merged): fp16-round + concat + fragment-order =================
#define A_BLOCKS 8192   // 2^21 uint4 / 256
#define B_BLOCKS 4096   // 2^20 uint4 / 256

__global__ __launch_bounds__(256) void convert_AB(const float* __restrict__ X,
                                                  const float* __restrict__ Hs,
                                                  const float* __restrict__ Wx,
                                                  const float* __restrict__ Wh,
                                                  const float* __restrict__ bx,
                                                  const float* __restrict__ bh) {
    if (blockIdx.x < A_BLOCKS) {
        size_t idx = (size_t)blockIdx.x * 256 + threadIdx.x;
        int lane = (int)(idx & 31);
        int ks   = (int)((idx >> 5) & 1);
        int m16  = (int)((idx >> 6) & 7);
        int kt   = (int)((idx >> 9) & 63);
        int mb   = (int)(idx >> 15);
        int qr = lane >> 2, qc = lane & 3;
        int R = mb * 128 + m16 * 16 + qr;
        int C = kt * 32 + ks * 16 + 2 * qc;

        const float* src = (C < 1024) ? X : Hs;
        int c0 = C & 1023;
        float2 r0a = *(const float2*)&src[(size_t)R * 1024 + c0];
        float2 r0b = *(const float2*)&src[(size_t)R * 1024 + c0 + 8];
        float2 r1a = *(const float2*)&src[(size_t)(R + 8) * 1024 + c0];
        float2 r1b = *(const float2*)&src[(size_t)(R + 8) * 1024 + c0 + 8];

        uint4 o;
        o.x = h2pack(r0a.x, r0a.y);
        o.y = h2pack(r1a.x, r1a.y);
        o.z = h2pack(r0b.x, r0b.y);
        o.w = h2pack(r1b.x, r1b.y);
        g_A[idx] = o;
    } else {
        size_t idx = (size_t)(blockIdx.x - A_BLOCKS) * 256 + threadIdx.x;
        int lane = (int)(idx & 31);
        int ks   = (int)((idx >> 5) & 1);
        int p    = (int)((idx >> 6) & 1);
        int wn   = (int)((idx >> 7) & 3);
        int kt   = (int)((idx >> 9) & 63);
        int nb   = (int)(idx >> 15);
        int qr = lane >> 2, qc = lane & 3;
        int C = kt * 32 + ks * 16 + 2 * qc;
        int N0 = nb * 128 + wn * 32 + p * 16 + qr;
        int N1 = N0 + 8;
        int sr0 = (N0 & 3) * 1024 + (N0 >> 2);    // n' = 4h+g -> row g*1024+h
        int sr1 = (N1 & 3) * 1024 + (N1 >> 2);

        const float* src = (C < 1024) ? Wx : Wh;
        int c0 = C & 1023;
        float2 w0a = *(const float2*)&src[(size_t)sr0 * 1024 + c0];
        float2 w0b = *(const float2*)&src[(size_t)sr0 * 1024 + c0 + 8];
        float2 w1a = *(const float2*)&src[(size_t)sr1 * 1024 + c0];
        float2 w1b = *(const float2*)&src[(size_t)sr1 * 1024 + c0 + 8];

        uint4 o;
        o.x = h2pack(w0a.x, w0a.y);
        o.y = h2pack(w0b.x, w0b.y);
        o.z = h2pack(w1a.x, w1a.y);
        o.w = h2pack(w1b.x, w1b.y);
        g_B[idx] = o;

        if (kt == 0 && ks == 0 && qc == 0) {
            g_bias[N0] = bx[sr0] + bh[sr0];
            g_bias[N1] = bx[sr1] + bh[sr1];
        }
    }
}

// ================= fused GEMM + LSTM epilogue (2 CTAs/SM, mbarrier pipeline) =================
__global__ __launch_bounds__(THREADS, 2) void lstm_gemm(const float* __restrict__ cin,
                                                        float* __restrict__ out) {
    extern __shared__ char smem[];
    float* smf = (float*)smem;
    const int tid  = threadIdx.x;
    const int lane = tid & 31;
    const int wid  = tid >> 5;
    const int wm   = wid >> 2;      // 2 warps over M (64 rows each)
    const int wn   = wid & 3;       // 4 warps over N (32 cols each)
    const int qr   = lane >> 2;
    const int qc   = lane & 3;

    const int mb = blockIdx.y;      // 0..63
    const int nb = blockIdx.x;      // 0..31
    const int m_base = mb * BM;
    const int hb = nb * 32;         // 32 h values per CTA

    uint32_t sb;
    asm("{ .reg .u64 t; cvta.to.shared.u64 t, %1; cvt.u32.u64 %0, t; }" : "=r"(sb) : "l"(smem));

    if (tid < 128) smf[OFF_BIAS / 4 + tid] = g_bias[nb * 128 + tid];
    if (tid == 0) {
#pragma unroll
        for (int s = 0; s < NSTAGES; s++) {
            MBARRIER_INIT(sb + OFF_FULL + 8 * s, THREADS);
            MBARRIER_INIT(sb + OFF_EMPTY + 8 * s, THREADS);
        }
    }
    __syncthreads();   // barriers initialized before any arrive

    float acc[4][4][4] = {};   // 4 m16-frags x 4 n8-frags

    const uint4* gA4 = g_A + ((size_t)mb * 64) * SUB_A_U4;
    const uint4* gB4 = g_B + ((size_t)nb * 64) * SUB_B_U4;

    // ---- prologue: produce tiles 0,1 into stages 0,1 (no empty wait needed) ----
#pragma unroll
    for (int s = 0; s < NSTAGES - 1; s++) {
        uint32_t base = sb + (uint32_t)s * STAGE_BYTES;
        const uint4* a_src = gA4 + (size_t)s * A_TILE_U4;
        const uint4* b_src = gB4 + (size_t)s * B_TILE_U4;
#pragma unroll
        for (int j = 0; j < 4; j++) {
            int ch = j * THREADS + tid;
            cpa16(base + (uint32_t)ch * 16u, a_src + ch);
            cpa16(base + (uint32_t)(A_BYTES + ch * 16), b_src + ch);
        }
        CPASYNC_ARRIVE(sb + OFF_FULL + 8 * s);
    }

#pragma unroll 1
    for (int it = 0; it < KITERS2; ++it) {
        // ---- produce tile j = it+2 into stage j%3 ----
        const int j = it + NSTAGES - 1;
        if (j < KITERS2) {
            const int s2 = j % NSTAGES;
            if (j >= NSTAGES) {
                MBARRIER_WAIT(sb + OFF_EMPTY + 8 * s2, ((j / NSTAGES) - 1) & 1);
            }
            uint32_t base = sb + (uint32_t)s2 * STAGE_BYTES;
            const uint4* a_src = gA4 + (size_t)j * A_TILE_U4;
            const uint4* b_src = gB4 + (size_t)j * B_TILE_U4;
#pragma unroll
            for (int jj = 0; jj < 4; jj++) {
                int ch = jj * THREADS + tid;
                cpa16(base + (uint32_t)ch * 16u, a_src + ch);
                cpa16(base + (uint32_t)(A_BYTES + ch * 16), b_src + ch);
            }
            CPASYNC_ARRIVE(sb + OFF_FULL + 8 * s2);
        }

        // ---- consume stage it%3 ----
        const int cur = it % NSTAGES;
        MBARRIER_WAIT(sb + OFF_FULL + 8 * cur, (it / NSTAGES) & 1);

        const uint4* sA = (const uint4*)(smem + cur * STAGE_BYTES) + lane;
        const uint4* sB = (const uint4*)(smem + cur * STAGE_BYTES + A_BYTES) + lane;

#pragma unroll
        for (int ks2 = 0; ks2 < 4; ks2++) {       // 4 x 16-K steps per iteration
            const int aoff = (ks2 >> 1) * SUB_A_U4 + (ks2 & 1) * 32;
            const int boff = (ks2 >> 1) * SUB_B_U4 + (ks2 & 1) * 32;
            uint4 a0 = sA[aoff + ((wm * 4 + 0) * 2) * 32];
            uint4 a1 = sA[aoff + ((wm * 4 + 1) * 2) * 32];
            uint4 a2 = sA[aoff + ((wm * 4 + 2) * 2) * 32];
            uint4 a3 = sA[aoff + ((wm * 4 + 3) * 2) * 32];
            uint4 b0 = sB[boff + ((wn * 2 + 0) * 2) * 32];
            uint4 b1 = sB[boff + ((wn * 2 + 1) * 2) * 32];
#pragma unroll
            for (int mf = 0; mf < 4; mf++) {
                const uint4& a = (mf == 0) ? a0 : (mf == 1) ? a1 : (mf == 2) ? a2 : a3;
                mma_f16(acc[mf][0], a, b0.x, b0.y);
                mma_f16(acc[mf][1], a, b0.z, b0.w);
                mma_f16(acc[mf][2], a, b1.x, b1.y);
                mma_f16(acc[mf][3], a, b1.z, b1.w);
            }
        }

        MBARRIER_ARRIVE(sb + OFF_EMPTY + 8 * cur);   // done reading this stage
    }

    // ---------------- fused epilogue ----------------
    __syncthreads();   // all warps done before overlaying stage region
    {
        const int col0 = wn * 32;
#pragma unroll
        for (int mf = 0; mf < 4; mf++) {
            int r = wm * 64 + mf * 16 + qr;
#pragma unroll
            for (int nf = 0; nf < 4; nf++) {
                int cL = col0 + nf * 8 + 2 * qc;
                *(float2*)&smf[r * EPI_STRIDE + cL] = make_float2(acc[mf][nf][0], acc[mf][nf][1]);
                *(float2*)&smf[(r + 8) * EPI_STRIDE + cL] = make_float2(acc[mf][nf][2], acc[mf][nf][3]);
            }
        }
    }
    __syncthreads();

    {
        const int hl = tid & 31;          // h within block (0..31)
        const int rg = tid >> 5;          // 0..7
        float4 bv = *(float4*)&smf[OFF_BIAS / 4 + hl * 4];
        const int h = hb + hl;
#pragma unroll 1
        for (int i = 0; i < 16; i++) {
            int r = i * 8 + rg;
            float4 gt = *(float4*)&smf[r * EPI_STRIDE + hl * 4];
            size_t oidx = (size_t)(m_base + r) * HH + h;
            float cc = cin[oidx];
            float ig = fast_sigmoid(gt.x + bv.x);
            float fg = fast_sigmoid(gt.y + bv.y);
            float g2 = fast_tanh(gt.z + bv.z);
            float og = fast_sigmoid(gt.w + bv.w);
            float nc = fg * cc + ig * g2;
            float nh = og * fast_tanh(nc);
            out[oidx] = nh;
            out[oidx + (size_t)BB * HH] = nh;
            out[oidx + 2 * (size_t)BB * HH] = nc;
        }
    }
}

// ================= launch =================
extern "C" void kernel_launch(void* const* d_in, const int* in_sizes, int n_in,
                              void* d_out, int out_size) {
    const float* X  = (const float*)d_in[0];
    const float* Hs = (const float*)d_in[1];
    const float* c  = (const float*)d_in[2];
    const float* Wx = (const float*)d_in[3];
    const float* Wh = (const float*)d_in[4];
    const float* bx = (const float*)d_in[5];
    const float* bh = (const float*)d_in[6];
    float* out = (float*)d_out;

    cudaFuncSetAttribute(lstm_gemm, cudaFuncAttributeMaxDynamicSharedMemorySize, SMEM_TOTAL);

    convert_AB<<<A_BLOCKS + B_BLOCKS, 256>>>(X, Hs, Wx, Wh, bx, bh);
    lstm_gemm<<<dim3(NNI / BN, BB / BM), THREADS, SMEM_TOTAL>>>(c, out);
}

// round 17
// speedup vs baseline: 1.1450x; 1.0447x over previous
#include <cuda_runtime.h>
#include <cuda_fp16.h>
#include <cstdint>
#include <cstddef>

// ---------------- problem dims ----------------
#define BB 8192
#define HH 1024
#define KTOT 2048            // concat K = I + H
#define NNI 4096             // interleaved gate dim n' = 4*h + g

// ---------------- GEMM tiling ----------------
#define BM 128
#define BN 128
#define THREADS 256                  // 8 warps: 2 (M) x 4 (N), warp tile 64x32
#define NSTAGES 3
#define KITERS2 32                   // mainloop iterations, 64 K each
#define SUB_A_U4 512                 // 32-K subtile (128 rows) in uint4
#define SUB_B_U4 512
#define A_TILE_U4 (2 * SUB_A_U4)     // 64-K stage A = 16KB
#define B_TILE_U4 (2 * SUB_B_U4)
#define A_BYTES (A_TILE_U4 * 16)     // 16384
#define B_BYTES (B_TILE_U4 * 16)     // 16384
#define STAGE_BYTES (A_BYTES + B_BYTES)        // 32768
#define STAGE_REGION (NSTAGES * STAGE_BYTES)   // 98304
#define EPI_STRIDE 132               // 128 + 4 pad floats per epilogue row
#define EPI_BYTES (BM * EPI_STRIDE * 4)        // 67584 (overlays stage region)
#define OFF_BIAS STAGE_REGION                  // 512 B of bias
#define OFF_FULL (STAGE_REGION + 512)          // 3 x 8B full barriers
#define OFF_EMPTY (STAGE_REGION + 512 + 24)    // 3 x 8B empty barriers
#define SMEM_TOTAL (STAGE_REGION + 1024)       // 99328 -> 2 CTAs/SM

// ---------------- scratch: fragment-ordered fp16 operands ----------------
// g_A: [mb(64)][kt32(64)][m16(8)][ks(2)][lane(32)] x uint4
//      uint4 = {h2(A[R][C..]), h2(A[R+8][C..]), h2(A[R][C+8..]), h2(A[R+8][C+8..])}
__device__ uint4 g_A[(size_t)BB * KTOT / 8];
// g_B: [nb(32)][kt32(64)][wn(4)][p(2)][ks(2)][lane(32)] x uint4
//      uint4 = {h2(B[N0][C..]), h2(B[N0][C+8..]), h2(B[N1][C..]), h2(B[N1][C+8..])},
//      N0 = nb*128 + wn*32 + p*16 + qr, N1 = N0+8
__device__ uint4 g_B[(size_t)NNI * KTOT / 8];
__device__ float g_bias[NNI];   // interleaved 4h+g

// ---------------- helpers ----------------
__device__ __forceinline__ void cpa16(uint32_t s, const void* g) {
    asm volatile("cp.async.cg.shared.global [%0], [%1], 16;" :: "r"(s), "l"(g));
}

__device__ __forceinline__ uint32_t h2pack(float lo, float hi) {
    __half2 h = __floats2half2_rn(lo, hi);
    return *reinterpret_cast<uint32_t*>(&h);
}

__device__ __forceinline__ void mma_f16(float* d, const uint4& a, uint32_t b0, uint32_t b1) {
    asm volatile(
        "mma.sync.aligned.m16n8k16.row.col.f32.f16.f16.f32 "
        "{%0,%1,%2,%3}, {%4,%5,%6,%7}, {%8,%9}, {%0,%1,%2,%3};"
        : "+f"(d[0]), "+f"(d[1]), "+f"(d[2]), "+f"(d[3])
        : "r"(a.x), "r"(a.y), "r"(a.z), "r"(a.w), "r"(b0), "r"(b1));
}

__device__ __forceinline__ float fast_sigmoid(float x) {
    return __fdividef(1.0f, 1.0f + __expf(-x));
}
__device__ __forceinline__ float fast_tanh(float x) {
    return __fmaf_rn(2.0f, __fdividef(1.0f, 1.0f + __expf(-2.0f * x)), -1.0f);
}

#define MBARRIER_INIT(addr, cnt) \
    asm volatile("mbarrier.init.shared.b64 [%0], %1;" :: "r"((uint32_t)(addr)), "r"((uint32_t)(cnt)) : "memory")

#define MBARRIER_ARRIVE(addr) \
    asm volatile("mbarrier.arrive.release.cta.shared::cta.b64 _, [%0];" :: "r"((uint32_t)(addr)) : "memory")

#define CPASYNC_ARRIVE(addr) \
    asm volatile("cp.async.mbarrier.arrive.noinc.shared::cta.b64 [%0];" :: "r"((uint32_t)(addr)) : "memory")

#define MBARRIER_WAIT(addr, par) do {                                              \
    uint32_t _m = (uint32_t)(addr); uint32_t _p = (uint32_t)(par); uint32_t _d;    \
    asm volatile("{\n\t.reg .pred p;\n\t"                                          \
        "mbarrier.try_wait.parity.acquire.cta.shared::cta.b64 p, [%1], %2;\n\t"    \
        "selp.b32 %0, 1, 0, p;\n\t}"                                               \
        : "=r"(_d) : "r"(_m), "r"(_p) : "memory");                                 \
    if (!_d) {                                                                     \
        asm volatile("{\n\t.reg .pred P1;\n\t"                                     \
            "W%=:\n\t"                                                             \
            "mbarrier.try_wait.parity.acquire.cta.shared::cta.b64 P1, [%0], %1, 0x989680;\n\t" \
            "@P1 bra.uni D%=;\n\t bra.uni W%=;\n\t D%=:\n\t}"                      \
            :: "r"(_m), "r"(_p) : "memory");                                       \
    } } while (0)

// ================= pre-pass (merged): fp16-round + concat + fragment-order =================
#define A_BLOCKS 8192   // 2^21 uint4 / 256
#define B_BLOCKS 4096   // 2^20 uint4 / 256

__global__ __launch_bounds__(256) void convert_AB(const float* __restrict__ X,
                                                  const float* __restrict__ Hs,
                                                  const float* __restrict__ Wx,
                                                  const float* __restrict__ Wh,
                                                  const float* __restrict__ bx,
                                                  const float* __restrict__ bh) {
    if (blockIdx.x < A_BLOCKS) {
        size_t idx = (size_t)blockIdx.x * 256 + threadIdx.x;
        int lane = (int)(idx & 31);
        int ks   = (int)((idx >> 5) & 1);
        int m16  = (int)((idx >> 6) & 7);
        int kt   = (int)((idx >> 9) & 63);
        int mb   = (int)(idx >> 15);
        int qr = lane >> 2, qc = lane & 3;
        int R = mb * 128 + m16 * 16 + qr;
        int C = kt * 32 + ks * 16 + 2 * qc;

        const float* src = (C < 1024) ? X : Hs;
        int c0 = C & 1023;
        float2 r0a = *(const float2*)&src[(size_t)R * 1024 + c0];
        float2 r0b = *(const float2*)&src[(size_t)R * 1024 + c0 + 8];
        float2 r1a = *(const float2*)&src[(size_t)(R + 8) * 1024 + c0];
        float2 r1b = *(const float2*)&src[(size_t)(R + 8) * 1024 + c0 + 8];

        uint4 o;
        o.x = h2pack(r0a.x, r0a.y);
        o.y = h2pack(r1a.x, r1a.y);
        o.z = h2pack(r0b.x, r0b.y);
        o.w = h2pack(r1b.x, r1b.y);
        g_A[idx] = o;
    } else {
        size_t idx = (size_t)(blockIdx.x - A_BLOCKS) * 256 + threadIdx.x;
        int lane = (int)(idx & 31);
        int ks   = (int)((idx >> 5) & 1);
        int p    = (int)((idx >> 6) & 1);
        int wn   = (int)((idx >> 7) & 3);
        int kt   = (int)((idx >> 9) & 63);
        int nb   = (int)(idx >> 15);
        int qr = lane >> 2, qc = lane & 3;
        int C = kt * 32 + ks * 16 + 2 * qc;
        int N0 = nb * 128 + wn * 32 + p * 16 + qr;
        int N1 = N0 + 8;
        int sr0 = (N0 & 3) * 1024 + (N0 >> 2);    // n' = 4h+g -> row g*1024+h
        int sr1 = (N1 & 3) * 1024 + (N1 >> 2);

        const float* src = (C < 1024) ? Wx : Wh;
        int c0 = C & 1023;
        float2 w0a = *(const float2*)&src[(size_t)sr0 * 1024 + c0];
        float2 w0b = *(const float2*)&src[(size_t)sr0 * 1024 + c0 + 8];
        float2 w1a = *(const float2*)&src[(size_t)sr1 * 1024 + c0];
        float2 w1b = *(const float2*)&src[(size_t)sr1 * 1024 + c0 + 8];

        uint4 o;
        o.x = h2pack(w0a.x, w0a.y);
        o.y = h2pack(w0b.x, w0b.y);
        o.z = h2pack(w1a.x, w1a.y);
        o.w = h2pack(w1b.x, w1b.y);
        g_B[idx] = o;

        if (kt == 0 && ks == 0 && qc == 0) {
            g_bias[N0] = bx[sr0] + bh[sr0];
            g_bias[N1] = bx[sr1] + bh[sr1];
        }
    }
}

// ================= fused GEMM + LSTM epilogue (2 CTAs/SM, split-producer mbarrier pipeline) =================
__global__ __launch_bounds__(THREADS, 2) void lstm_gemm(const float* __restrict__ cin,
                                                        float* __restrict__ out) {
    extern __shared__ char smem[];
    float* smf = (float*)smem;
    const int tid  = threadIdx.x;
    const int lane = tid & 31;
    const int wid  = tid >> 5;
    const int wm   = wid >> 2;      // 2 warps over M (64 rows each)
    const int wn   = wid & 3;       // 4 warps over N (32 cols each)
    const int qr   = lane >> 2;
    const int qc   = lane & 3;
    const int grpA = (wid < 4);     // produce-duty group: A -> even tiles, B -> odd tiles
    const int pt   = tid & 127;     // thread index within produce group

    const int mb = blockIdx.y;      // 0..63
    const int nb = blockIdx.x;      // 0..31
    const int m_base = mb * BM;
    const int hb = nb * 32;         // 32 h values per CTA

    uint32_t sb;
    asm("{ .reg .u64 t; cvta.to.shared.u64 t, %1; cvt.u32.u64 %0, t; }" : "=r"(sb) : "l"(smem));

    if (tid < 128) smf[OFF_BIAS / 4 + tid] = g_bias[nb * 128 + tid];
    if (tid == 0) {
#pragma unroll
        for (int s = 0; s < NSTAGES; s++) {
            MBARRIER_INIT(sb + OFF_FULL + 8 * s, 128);  // one producing group (128 threads)
            MBARRIER_INIT(sb + OFF_EMPTY + 8 * s, 8);   // one elected arrive per warp
        }
    }
    __syncthreads();   // barriers initialized before any arrive

    float acc[4][4][4] = {};   // 4 m16-frags x 4 n8-frags

    const uint4* gA4 = g_A + ((size_t)mb * 64) * SUB_A_U4;
    const uint4* gB4 = g_B + ((size_t)nb * 64) * SUB_B_U4;

    // ---- prologue: group A produces tile 0, group B produces tile 1 ----
    {
        const int s = grpA ? 0 : 1;
        uint32_t base = sb + (uint32_t)s * STAGE_BYTES;
        const uint4* a_src = gA4 + (size_t)s * A_TILE_U4;
        const uint4* b_src = gB4 + (size_t)s * B_TILE_U4;
#pragma unroll
        for (int jj = 0; jj < 8; jj++) {
            int ch = jj * 128 + pt;
            cpa16(base + (uint32_t)ch * 16u, a_src + ch);
            cpa16(base + (uint32_t)(A_BYTES + ch * 16), b_src + ch);
        }
        CPASYNC_ARRIVE(sb + OFF_FULL + 8 * s);
    }

#pragma unroll 1
    for (int it = 0; it < KITERS2; ++it) {
        // ---- consume stage it%3 first ----
        const int cur = it % NSTAGES;
        MBARRIER_WAIT(sb + OFF_FULL + 8 * cur, (it / NSTAGES) & 1);

        const uint4* sA = (const uint4*)(smem + cur * STAGE_BYTES) + lane;
        const uint4* sB = (const uint4*)(smem + cur * STAGE_BYTES + A_BYTES) + lane;

#pragma unroll
        for (int ks2 = 0; ks2 < 4; ks2++) {       // 4 x 16-K steps per iteration
            const int aoff = (ks2 >> 1) * SUB_A_U4 + (ks2 & 1) * 32;
            const int boff = (ks2 >> 1) * SUB_B_U4 + (ks2 & 1) * 32;
            uint4 a0 = sA[aoff + ((wm * 4 + 0) * 2) * 32];
            uint4 a1 = sA[aoff + ((wm * 4 + 1) * 2) * 32];
            uint4 a2 = sA[aoff + ((wm * 4 + 2) * 2) * 32];
            uint4 a3 = sA[aoff + ((wm * 4 + 3) * 2) * 32];
            uint4 b0 = sB[boff + ((wn * 2 + 0) * 2) * 32];
            uint4 b1 = sB[boff + ((wn * 2 + 1) * 2) * 32];
#pragma unroll
            for (int mf = 0; mf < 4; mf++) {
                const uint4& a = (mf == 0) ? a0 : (mf == 1) ? a1 : (mf == 2) ? a2 : a3;
                mma_f16(acc[mf][0], a, b0.x, b0.y);
                mma_f16(acc[mf][1], a, b0.z, b0.w);
                mma_f16(acc[mf][2], a, b1.x, b1.y);
                mma_f16(acc[mf][3], a, b1.z, b1.w);
            }
        }
        if (lane == 0) MBARRIER_ARRIVE(sb + OFF_EMPTY + 8 * cur);   // warp done reading

        // ---- then produce tile j = it+2 into stage j%3 (alternating duty) ----
        const int j = it + NSTAGES - 1;
        if (j < KITERS2 && ((j & 1) == 0) == grpA) {
            const int s2 = j % NSTAGES;
            if (j >= NSTAGES) {
                MBARRIER_WAIT(sb + OFF_EMPTY + 8 * s2, ((j / NSTAGES) - 1) & 1);
            }
            uint32_t base = sb + (uint32_t)s2 * STAGE_BYTES;
            const uint4* a_src = gA4 + (size_t)j * A_TILE_U4;
            const uint4* b_src = gB4 + (size_t)j * B_TILE_U4;
#pragma unroll
            for (int jj = 0; jj < 8; jj++) {
                int ch = jj * 128 + pt;
                cpa16(base + (uint32_t)ch * 16u, a_src + ch);
                cpa16(base + (uint32_t)(A_BYTES + ch * 16), b_src + ch);
            }
            CPASYNC_ARRIVE(sb + OFF_FULL + 8 * s2);
        }
    }

    // ---------------- fused epilogue ----------------
    __syncthreads();   // all warps done before overlaying stage region
    {
        const int col0 = wn * 32;
#pragma unroll
        for (int mf = 0; mf < 4; mf++) {
            int r = wm * 64 + mf * 16 + qr;
#pragma unroll
            for (int nf = 0; nf < 4; nf++) {
                int cL = col0 + nf * 8 + 2 * qc;
                *(float2*)&smf[r * EPI_STRIDE + cL] = make_float2(acc[mf][nf][0], acc[mf][nf][1]);
                *(float2*)&smf[(r + 8) * EPI_STRIDE + cL] = make_float2(acc[mf][nf][2], acc[mf][nf][3]);
            }
        }
    }
    __syncthreads();

    {
        const int hl = tid & 31;          // h within block (0..31)
        const int rg = tid >> 5;          // 0..7
        float4 bv = *(float4*)&smf[OFF_BIAS / 4 + hl * 4];
        const int h = hb + hl;
#pragma unroll 1
        for (int i = 0; i < 16; i++) {
            int r = i * 8 + rg;
            float4 gt = *(float4*)&smf[r * EPI_STRIDE + hl * 4];
            size_t oidx = (size_t)(m_base + r) * HH + h;
            float cc = cin[oidx];
            float ig = fast_sigmoid(gt.x + bv.x);
            float fg = fast_sigmoid(gt.y + bv.y);
            float g2 = fast_tanh(gt.z + bv.z);
            float og = fast_sigmoid(gt.w + bv.w);
            float nc = fg * cc + ig * g2;
            float nh = og * fast_tanh(nc);
            out[oidx] = nh;
            out[oidx + (size_t)BB * HH] = nh;
            out[oidx + 2 * (size_t)BB * HH] = nc;
        }
    }
}

// ================= launch =================
extern "C" void kernel_launch(void* const* d_in, const int* in_sizes, int n_in,
                              void* d_out, int out_size) {
    const float* X  = (const float*)d_in[0];
    const float* Hs = (const float*)d_in[1];
    const float* c  = (const float*)d_in[2];
    const float* Wx = (const float*)d_in[3];
    const float* Wh = (const float*)d_in[4];
    const float* bx = (const float*)d_in[5];
    const float* bh = (const float*)d_in[6];
    float* out = (float*)d_out;

    cudaFuncSetAttribute(lstm_gemm, cudaFuncAttributeMaxDynamicSharedMemorySize, SMEM_TOTAL);

    convert_AB<<<A_BLOCKS + B_BLOCKS, 256>>>(X, Hs, Wx, Wh, bx, bh);
    lstm_gemm<<<dim3(NNI / BN, BB / BM), THREADS, SMEM_TOTAL>>>(c, out);
}